// round 15
// baseline (speedup 1.0000x reference)
#include <cuda_runtime.h>
#include <cstdint>

// Bidirectional tanh-Elman RNN, B=32, S=2048, D=H=256, fp32.
//
// Phase 1 (xp_kernel): xp[dir] = x @ Wx_dir + b_dir  -> 128MB device scratch
//   (2-col x 32-row register blocking, FFMA2 — unchanged from R14).
// Phase 2 (rnn_kernel): 64 clusters of 2 CTAs; cluster = one (dir, batch).
//   R7 protocol events verbatim (arm t0 at top / st.async / sync / try_wait
//   by ALL threads). Compute split per thread into:
//     early dot: 64 local k (h this CTA wrote) — computed BEFORE try_wait,
//                overlapping the DSMEM delivery window;
//     late dot : 64 remote k — the only dot on the post-wake critical path.
//   Partials of a j-column live in paired lanes (l ^ 16): combined by one
//   shfl_xor instead of the old sRed smem reduction + extra __syncthreads.

#define S_SZ 2048
#define H_SZ 256
#define B_SZ 32

__device__ float g_xp[2u * 65536u * 256u];   // [dir][b*S + s][j]  128 MB scratch

__device__ __forceinline__ unsigned long long pack2(float a, float b) {
    unsigned long long r;
    asm("mov.b64 %0, {%1, %2};" : "=l"(r)
        : "r"(__float_as_uint(a)), "r"(__float_as_uint(b)));
    return r;
}
__device__ __forceinline__ void unpack2(unsigned long long p, float& a, float& b) {
    unsigned int lo, hi;
    asm("mov.b64 {%0, %1}, %2;" : "=r"(lo), "=r"(hi) : "l"(p));
    a = __uint_as_float(lo);
    b = __uint_as_float(hi);
}
__device__ __forceinline__ unsigned long long splat2(float a) {
    unsigned long long r;
    asm("mov.b64 %0, {%1, %1};" : "=l"(r) : "r"(__float_as_uint(a)));
    return r;
}
#define FMA2(acc, a, b) \
    asm("fma.rn.f32x2 %0, %1, %2, %0;" : "+l"(acc) : "l"(a), "l"(b))

// MUFU-based tanh: abs err ~1e-7
__device__ __forceinline__ float fast_tanh(float z) {
    float e = __expf(2.0f * z);
    return 1.0f - __fdividef(2.0f, e + 1.0f);
}

// ---------------------------------------------------------------------------
// Phase 1: input projection GEMM (unchanged from R14)
// ---------------------------------------------------------------------------
#define XP_ROWS 64
#define XP_KC   64
#define XP_SMEM_FLOATS (XP_KC * 256 + XP_KC * 64)   // 20480 floats

__global__ __launch_bounds__(256, 2) void xp_kernel(
    const float* __restrict__ x,
    const float* __restrict__ Wx_f, const float* __restrict__ b_f,
    const float* __restrict__ Wx_b, const float* __restrict__ b_b)
{
    extern __shared__ float sm[];
    float* sW  = sm;                 // [64][256]
    float* sXT = sm + XP_KC * 256;   // [64][64]

    const int dir  = blockIdx.y;
    const int row0 = blockIdx.x * XP_ROWS;
    const float* W    = dir ? Wx_b : Wx_f;
    const float* bias = dir ? b_b  : b_f;
    const int t  = threadIdx.x;
    const int jp = t & 127;
    const int rg = t >> 7;

    unsigned long long accA[16], accB[16];
    {
        unsigned long long ba = splat2(bias[jp]);
        unsigned long long bb = splat2(bias[jp + 128]);
        #pragma unroll
        for (int p = 0; p < 16; ++p) { accA[p] = ba; accB[p] = bb; }
    }

    for (int i0 = 0; i0 < H_SZ; i0 += XP_KC) {
        for (int idx = t; idx < XP_KC * 256; idx += 256)
            sW[idx] = W[(i0 + (idx >> 8)) * H_SZ + (idx & 255)];
        {
            int r  = t >> 2;
            int iq = (t & 3) * 16;
            const float* xr = x + (size_t)(row0 + r) * H_SZ + i0 + iq;
            #pragma unroll
            for (int k = 0; k < 4; ++k) {
                float4 v = *(const float4*)(xr + k * 4);
                sXT[(iq + k*4 + 0) * 64 + r] = v.x;
                sXT[(iq + k*4 + 1) * 64 + r] = v.y;
                sXT[(iq + k*4 + 2) * 64 + r] = v.z;
                sXT[(iq + k*4 + 3) * 64 + r] = v.w;
            }
        }
        __syncthreads();
        for (int ii = 0; ii < XP_KC; ++ii) {
            unsigned long long wa = splat2(sW[ii * 256 + jp]);
            unsigned long long wb = splat2(sW[ii * 256 + jp + 128]);
            const ulonglong2* xv = (const ulonglong2*)(sXT + ii * 64 + rg * 32);
            #pragma unroll
            for (int q = 0; q < 8; ++q) {
                ulonglong2 v = xv[q];
                FMA2(accA[2*q + 0], v.x, wa);
                FMA2(accA[2*q + 1], v.y, wa);
                FMA2(accB[2*q + 0], v.x, wb);
                FMA2(accB[2*q + 1], v.y, wb);
            }
        }
        __syncthreads();
    }
    float* dst = g_xp + ((size_t)dir * 65536u + row0 + rg * 32) * 256;
    #pragma unroll
    for (int p = 0; p < 16; ++p) {
        float a0, a1, b0, b1;
        unpack2(accA[p], a0, a1);
        unpack2(accB[p], b0, b1);
        dst[(size_t)(2*p + 0) * 256 + jp]       = a0;
        dst[(size_t)(2*p + 1) * 256 + jp]       = a1;
        dst[(size_t)(2*p + 0) * 256 + jp + 128] = b0;
        dst[(size_t)(2*p + 1) * 256 + jp + 128] = b1;
    }
}

// ---------------------------------------------------------------------------
// Phase 2: recurrence (early/late k-quarter split + shfl combine).
// ---------------------------------------------------------------------------
__device__ __forceinline__ uint32_t smem_u32(const void* p) {
    uint32_t a;
    asm("{ .reg .u64 tmp; cvta.to.shared.u64 tmp, %1; cvt.u32.u64 %0, tmp; }"
        : "=r"(a) : "l"(p));
    return a;
}

__global__ __launch_bounds__(256, 1) __cluster_dims__(2, 1, 1)
void rnn_kernel(const float* __restrict__ Wh_f,
                const float* __restrict__ Wh_b,
                float* __restrict__ out)
{
    __shared__ __align__(16) float sH[2][H_SZ];   // full h, double-buffered
    __shared__ __align__(8) unsigned long long sBar;

    const int t    = threadIdx.x;
    const int rank = blockIdx.x & 1;       // j-half owned by this CTA
    const int c    = blockIdx.x >> 1;
    const int dir  = c >> 5;
    const int b    = c & 31;
    const int wid  = t >> 5;
    const int l    = t & 31;
    const int jl    = wid * 16 + (l & 15); // 0..127: this thread's j column
    const int jglob = rank * 128 + jl;
    const int half  = l >> 4;              // which k-sub-quarter of the pair
    const bool isFin = (half == 0);        // lanes 0-15 finalize/tanh/send

    // k quarters (64 k each): early = inside this CTA's own h half,
    // late = inside the peer's half.
    const int kq_e = half + rank * 2;
    const int kq_l = half + (1 - rank) * 2;

    const float* Wh = dir ? Wh_b : Wh_f;

    unsigned long long we[32], wl2[32];
    #pragma unroll
    for (int ii = 0; ii < 32; ++ii) {
        we[ii]  = pack2(Wh[(kq_e * 64 + 2*ii + 0) * H_SZ + jglob],
                        Wh[(kq_e * 64 + 2*ii + 1) * H_SZ + jglob]);
        wl2[ii] = pack2(Wh[(kq_l * 64 + 2*ii + 0) * H_SZ + jglob],
                        Wh[(kq_l * 64 + 2*ii + 1) * H_SZ + jglob]);
    }

    sH[0][t] = 0.0f;
    const uint32_t barLocal = smem_u32(&sBar);
    const uint32_t shBase   = smem_u32(&sH[0][0]);
    if (t == 0)
        asm volatile("mbarrier.init.shared.b64 [%0], %1;" :: "r"(barLocal), "r"(1) : "memory");
    __syncthreads();
    asm volatile("barrier.cluster.arrive.aligned;" ::: "memory");
    asm volatile("barrier.cluster.wait.aligned;"   ::: "memory");

    uint32_t peerBar, peerSh;
    {
        uint32_t pr = rank ^ 1;
        asm("mapa.shared::cluster.u32 %0, %1, %2;" : "=r"(peerBar) : "r"(barLocal), "r"(pr));
        asm("mapa.shared::cluster.u32 %0, %1, %2;" : "=r"(peerSh)  : "r"(shBase),   "r"(pr));
    }

    const float* xp_base  = g_xp + ((size_t)dir * 65536u + (size_t)b * S_SZ) * 256 + jglob;
    float*       out_base = out + (size_t)b * S_SZ * 512 + dir * 256 + jglob;

    int sx = dir ? (S_SZ - 1) : 0;
    const int sstep = dir ? -1 : 1;
    float xpv   = isFin ? __ldg(xp_base + (size_t)sx * 256) : 0.0f;
    float early = 0.0f;                    // early (local-k) partial for step 0: h=0

    for (int s = 0; s < S_SZ; ++s) {
        // arm generation s (t0; all threads passed try_wait(s-1) last iter,
        // so this arrival provably lands in phase s; tx-before-expect within
        // a phase is legal and was exercised by the R7/R12/R14 kernels)
        if (t == 0 && s + 1 < S_SZ)
            asm volatile("mbarrier.arrive.expect_tx.shared.b64 _, [%0], %1;"
                         :: "r"(barLocal), "r"(512) : "memory");

        // prefetch next step's xp (finalizer lanes only)
        float xpn = 0.0f;
        if (isFin && s + 1 < S_SZ)
            xpn = __ldg(xp_base + (size_t)(sx + sstep) * 256);

        // LATE dot: 64 remote k (peer half of h(s), valid since try_wait(s-1))
        {
            const float* hb = sH[s & 1] + kq_l * 64;
            unsigned long long p0 = 0ull, p1 = 0ull;
            #pragma unroll
            for (int q = 0; q < 16; ++q) {
                ulonglong2 hv = *(const ulonglong2*)(hb + (q << 2));
                FMA2(p0, hv.x, wl2[2*q + 0]);
                FMA2(p1, hv.y, wl2[2*q + 1]);
            }
            float a0, a1, a2, a3;
            unpack2(p0, a0, a1);
            unpack2(p1, a2, a3);
            early += (a0 + a1) + (a2 + a3);   // early partial + late partial
        }

        // combine the two lane-partials of this j column (lanes l and l^16)
        float sum = early + __shfl_xor_sync(0xffffffffu, early, 16);

        const int nb = (s + 1) & 1;
        if (isFin) {
            float hnew = fast_tanh(sum + xpv);
            sH[nb][jglob] = hnew;                       // local copy
            out_base[(size_t)sx * 512] = hnew;          // output
            if (s + 1 < S_SZ) {
                uint32_t dst = peerSh + (uint32_t)(nb * 256 + jglob) * 4u;
                asm volatile(
                    "st.async.shared::cluster.mbarrier::complete_tx::bytes.u32 [%0], %1, [%2];"
                    :: "r"(dst), "r"(__float_as_uint(hnew)), "r"(peerBar) : "memory");
            }
        }
        xpv = xpn;
        __syncthreads();   // local half of sH[nb] visible to all warps

        if (s + 1 < S_SZ) {
            // EARLY dot for step s+1: 64 local k of h(s+1) — overlaps the
            // in-flight DSMEM delivery of the peer half
            const float* hb = sH[nb] + kq_e * 64;
            unsigned long long p0 = 0ull, p1 = 0ull;
            #pragma unroll
            for (int q = 0; q < 16; ++q) {
                ulonglong2 hv = *(const ulonglong2*)(hb + (q << 2));
                FMA2(p0, hv.x, we[2*q + 0]);
                FMA2(p1, hv.y, we[2*q + 1]);
            }
            float a0, a1, a2, a3;
            unpack2(p0, a0, a1);
            unpack2(p1, a2, a3);
            early = (a0 + a1) + (a2 + a3);

            // wait for peer half of h(s+1) (generation s, parity s&1) — ALL threads
            uint32_t parity = (uint32_t)(s & 1);
            asm volatile(
                "{\n\t.reg .pred P;\n\t"
                "WL_%=:\n\t"
                "mbarrier.try_wait.parity.acquire.cluster.shared::cta.b64 P, [%0], %1, 0x989680;\n\t"
                "@!P bra WL_%=;\n\t}"
                :: "r"(barLocal), "r"(parity) : "memory");
        }
        sx += sstep;
    }
}

// ---------------------------------------------------------------------------
extern "C" void kernel_launch(void* const* d_in, const int* in_sizes, int n_in,
                              void* d_out, int out_size)
{
    const float* x    = (const float*)d_in[0];
    const float* Wx_f = (const float*)d_in[1];
    const float* Wh_f = (const float*)d_in[2];
    const float* b_f  = (const float*)d_in[3];
    const float* Wx_b = (const float*)d_in[4];
    const float* Wh_b = (const float*)d_in[5];
    const float* b_b  = (const float*)d_in[6];
    float* out = (float*)d_out;

    cudaFuncSetAttribute(xp_kernel, cudaFuncAttributeMaxDynamicSharedMemorySize,
                         XP_SMEM_FLOATS * 4);

    dim3 xpgrid(65536 / XP_ROWS, 2);
    xp_kernel<<<xpgrid, 256, XP_SMEM_FLOATS * 4>>>(x, Wx_f, b_f, Wx_b, b_b);
    rnn_kernel<<<128, 256>>>(Wh_f, Wh_b, out);
}